// round 6
// baseline (speedup 1.0000x reference)
#include <cuda_runtime.h>
#include <cuda_bf16.h>
#include <cstdint>

// Problem constants (from reference)
#define N_NODES 50000
#define N_EDGES 800000
#define D_IN    128
#define D_OUT   128

// Scratch: support = X @ W  (25.6 MB). Static __device__ array (no allocs allowed).
__device__ float g_support[(size_t)N_NODES * D_OUT];

// ---------------------------------------------------------------------------
// Kernel 1: SGEMM  support[M,128] = X[M,128] @ W[128,128]
// 128x128 tile, BK=16, 8x8 per-thread micro-tile, 256 threads.
// ---------------------------------------------------------------------------
#define BM 128
#define BN 128
#define BK 16
#define TM 8
#define TN 8

__global__ __launch_bounds__(256) void gemm_kernel(const float* __restrict__ X,
                                                   const float* __restrict__ W) {
    __shared__ float As[BK][BM];
    __shared__ float Bs[BK][BN];

    const int block_row = blockIdx.x * BM;
    const int tid = threadIdx.x;
    const int tx = tid & 15;   // 0..15  -> col group (TN=8)
    const int ty = tid >> 4;   // 0..15  -> row group (TM=8)

    float acc[TM][TN];
#pragma unroll
    for (int i = 0; i < TM; i++)
#pragma unroll
        for (int j = 0; j < TN; j++) acc[i][j] = 0.0f;

    for (int k0 = 0; k0 < D_IN; k0 += BK) {
        // Load A tile: 128 rows x 16 cols = 512 float4, 2 per thread.
        // Store transposed into As[k][m] for conflict-free compute reads.
#pragma unroll
        for (int i = 0; i < 2; i++) {
            int idx = tid + i * 256;        // 0..511
            int r   = idx >> 2;             // row in tile 0..127
            int c4  = idx & 3;              // which float4 of the 16 cols
            int grow = block_row + r;
            float4 a = (grow < N_NODES)
                ? *(const float4*)&X[(size_t)grow * D_IN + k0 + c4 * 4]
                : make_float4(0.f, 0.f, 0.f, 0.f);
            As[c4 * 4 + 0][r] = a.x;
            As[c4 * 4 + 1][r] = a.y;
            As[c4 * 4 + 2][r] = a.z;
            As[c4 * 4 + 3][r] = a.w;
        }
        // Load B tile: 16 rows x 128 cols = 512 float4, 2 per thread.
#pragma unroll
        for (int i = 0; i < 2; i++) {
            int idx = tid + i * 256;
            int r   = idx >> 5;             // 0..15
            int c4  = idx & 31;             // 0..31
            *(float4*)&Bs[r][c4 * 4] =
                *(const float4*)&W[(size_t)(k0 + r) * D_OUT + c4 * 4];
        }
        __syncthreads();

#pragma unroll
        for (int k = 0; k < BK; k++) {
            float ra[TM], rb[TN];
#pragma unroll
            for (int i = 0; i < TM; i++) ra[i] = As[k][ty * TM + i];
#pragma unroll
            for (int j = 0; j < TN; j++) rb[j] = Bs[k][tx * TN + j];
#pragma unroll
            for (int i = 0; i < TM; i++)
#pragma unroll
                for (int j = 0; j < TN; j++) acc[i][j] += ra[i] * rb[j];
        }
        __syncthreads();
    }

    // Store 8x8 per-thread tile (two float4 per row).
#pragma unroll
    for (int i = 0; i < TM; i++) {
        int row = block_row + ty * TM + i;
        if (row < N_NODES) {
            float* outp = &g_support[(size_t)row * D_OUT + tx * TN];
            *(float4*)&outp[0] = make_float4(acc[i][0], acc[i][1], acc[i][2], acc[i][3]);
            *(float4*)&outp[4] = make_float4(acc[i][4], acc[i][5], acc[i][6], acc[i][7]);
        }
    }
}

// ---------------------------------------------------------------------------
// Kernel 2: out[n, :] = bias[:]   (initializes the poisoned output buffer)
// ---------------------------------------------------------------------------
__global__ __launch_bounds__(256) void bias_init_kernel(const float* __restrict__ bias,
                                                        float* __restrict__ out) {
    __shared__ float4 b4[D_OUT / 4];
    if (threadIdx.x < D_OUT / 4)
        b4[threadIdx.x] = *(const float4*)&bias[threadIdx.x * 4];
    __syncthreads();

    size_t total4 = (size_t)N_NODES * D_OUT / 4;
    size_t idx = (size_t)blockIdx.x * blockDim.x + threadIdx.x;
    size_t stride = (size_t)gridDim.x * blockDim.x;
    for (; idx < total4; idx += stride) {
        ((float4*)out)[idx] = b4[idx & (D_OUT / 4 - 1)];
    }
}

// ---------------------------------------------------------------------------
// Kernel 3: SpMM scatter.  adj_dst is SORTED, so each warp takes a contiguous
// chunk of edges, accumulates a full 128-wide row in registers (float4/lane)
// while dst stays constant, and flushes with atomicAdd on segment boundaries.
// Indices are int32 (JAX x64-disabled downcasts the reference's int64).
// Defensive range guards turn any residual dtype mismatch into a wrong-answer
// (diagnosable via rel_err) instead of an illegal access.
// ---------------------------------------------------------------------------
#define EDGES_PER_WARP 128

__global__ __launch_bounds__(256) void spmm_kernel(const int* __restrict__ src,
                                                   const int* __restrict__ dst,
                                                   const float* __restrict__ val,
                                                   float* __restrict__ out) {
    const int warp_id = (blockIdx.x * blockDim.x + threadIdx.x) >> 5;
    const int lane    = threadIdx.x & 31;
    const int lane4   = lane * 4;

    int e0 = warp_id * EDGES_PER_WARP;
    if (e0 >= N_EDGES) return;
    int e1 = e0 + EDGES_PER_WARP;
    if (e1 > N_EDGES) e1 = N_EDGES;

    float4 acc = make_float4(0.f, 0.f, 0.f, 0.f);

    // Prefetched edge metadata (uniform across warp -> broadcast loads).
    int   cur_dst = dst[e0];
    int   nd = cur_dst;
    int   ns = src[e0];
    float nv = val[e0];

    for (int e = e0; e < e1; e++) {
        int   d = nd;
        int   s = ns;
        float v = nv;
        // Prefetch next edge's metadata before the dependent gather.
        if (e + 1 < e1) {
            nd = dst[e + 1];
            ns = src[e + 1];
            nv = val[e + 1];
        }
        if (d != cur_dst) {
            // flush finished segment
            if (cur_dst >= 0 && cur_dst < N_NODES) {
                float* o = &out[(size_t)cur_dst * D_OUT + lane4];
                atomicAdd(&o[0], acc.x);
                atomicAdd(&o[1], acc.y);
                atomicAdd(&o[2], acc.z);
                atomicAdd(&o[3], acc.w);
            }
            acc = make_float4(0.f, 0.f, 0.f, 0.f);
            cur_dst = d;
        }
        if (s >= 0 && s < N_NODES) {
            float4 sup = *(const float4*)&g_support[(size_t)s * D_OUT + lane4];
            acc.x += v * sup.x;
            acc.y += v * sup.y;
            acc.z += v * sup.z;
            acc.w += v * sup.w;
        }
    }
    // final flush
    if (cur_dst >= 0 && cur_dst < N_NODES) {
        float* o = &out[(size_t)cur_dst * D_OUT + lane4];
        atomicAdd(&o[0], acc.x);
        atomicAdd(&o[1], acc.y);
        atomicAdd(&o[2], acc.z);
        atomicAdd(&o[3], acc.w);
    }
}

// ---------------------------------------------------------------------------
// Launch
// Inputs (metadata order): x, adj_src, adj_dst, adj_val, weight, bias
// ---------------------------------------------------------------------------
extern "C" void kernel_launch(void* const* d_in, const int* in_sizes, int n_in,
                              void* d_out, int out_size) {
    const float* x      = (const float*)d_in[0];
    const int*   adjsrc = (const int*)d_in[1];
    const int*   adjdst = (const int*)d_in[2];
    const float* adjval = (const float*)d_in[3];
    const float* weight = (const float*)d_in[4];
    const float* bias   = (const float*)d_in[5];
    float*       out    = (float*)d_out;

    // 1) support = X @ W
    int gemm_blocks = (N_NODES + BM - 1) / BM;   // 391
    gemm_kernel<<<gemm_blocks, 256>>>(x, weight);

    // 2) out = bias (broadcast)
    bias_init_kernel<<<1184, 256>>>(bias, out);

    // 3) out += segment_sum(val * support[src], dst)
    int n_warps  = (N_EDGES + EDGES_PER_WARP - 1) / EDGES_PER_WARP;  // 6250
    int n_blocks = (n_warps + 7) / 8;                                // 782
    spmm_kernel<<<n_blocks, 256>>>(adjsrc, adjdst, adjval, out);
}

// round 7
// speedup vs baseline: 1.3874x; 1.3874x over previous
#include <cuda_runtime.h>
#include <cuda_bf16.h>
#include <cstdint>

// Problem constants (from reference)
#define N_NODES 50000
#define N_EDGES 800000
#define D_IN    128
#define D_OUT   128

// Scratch: support = X @ W  (25.6 MB). Static __device__ array (no allocs allowed).
__device__ float g_support[(size_t)N_NODES * D_OUT];

// ---------------------------------------------------------------------------
// Kernel 1: tf32 tensor-core GEMM  support[M,128] = X[M,128] @ W[128,128]
// BM=128, BK=32, 256 threads = 8 warps in a 4(m) x 2(n) grid.
// Warp tile 32x64 = 2 m-tiles x 8 n-tiles of mma.m16n8k8.tf32.
// fp32 -> tf32 (round-to-nearest) at smem store; fp32 accumulate.
// ---------------------------------------------------------------------------
#define BM   128
#define BKT  32
#define APAD 4   // As stride 36 floats: bank = (lane + c) mod 32 -> conflict-free
#define BPAD 4   // Bs stride 132 floats: bank = 4*(lane%4)+(lane/4)+c -> conflict-free

__device__ __forceinline__ float f2tf32(float x) {
    uint32_t u;
    asm("cvt.rna.tf32.f32 %0, %1;" : "=r"(u) : "f"(x));
    return __uint_as_float(u);
}

__device__ __forceinline__ void mma_tf32(float* c, const uint32_t* a,
                                         uint32_t b0, uint32_t b1) {
    asm volatile(
        "mma.sync.aligned.m16n8k8.row.col.f32.tf32.tf32.f32 "
        "{%0,%1,%2,%3}, {%4,%5,%6,%7}, {%8,%9}, {%0,%1,%2,%3};\n"
        : "+f"(c[0]), "+f"(c[1]), "+f"(c[2]), "+f"(c[3])
        : "r"(a[0]), "r"(a[1]), "r"(a[2]), "r"(a[3]), "r"(b0), "r"(b1));
}

__global__ __launch_bounds__(256, 2) void gemm_tc_kernel(const float* __restrict__ X,
                                                         const float* __restrict__ W) {
    __shared__ float As[BM][BKT + APAD];     // 128 x 36  (18.4 KB)
    __shared__ float Bs[BKT][D_OUT + BPAD];  // 32 x 132  (16.9 KB)

    const int tid  = threadIdx.x;
    const int wid  = tid >> 5;
    const int lane = tid & 31;
    const int block_row = blockIdx.x * BM;

    const int warp_m = (wid & 3) * 32;   // 0,32,64,96
    const int warp_n = (wid >> 2) * 64;  // 0,64
    const int lq = lane >> 2;            // 0..7
    const int lr = lane & 3;             // 0..3

    float acc[2][8][4];
#pragma unroll
    for (int mt = 0; mt < 2; mt++)
#pragma unroll
        for (int nt = 0; nt < 8; nt++)
#pragma unroll
            for (int i = 0; i < 4; i++) acc[mt][nt][i] = 0.0f;

    // Register-staged tiles. A tile: 128x32 = 1024 float4 -> 4/thread.
    //                        B tile:  32x128 = 1024 float4 -> 4/thread.
    float4 aR[4], bR[4];

    // Prefetch kb=0.
#pragma unroll
    for (int i = 0; i < 4; i++) {
        int idx = tid + i * 256;
        int ar  = idx >> 3;          // 0..127
        int ac4 = idx & 7;           // 0..7
        int grow = block_row + ar;
        aR[i] = (grow < N_NODES)
            ? *(const float4*)&X[(size_t)grow * D_IN + ac4 * 4]
            : make_float4(0.f, 0.f, 0.f, 0.f);
        int br  = idx >> 5;          // 0..31
        int bc4 = idx & 31;          // 0..31
        bR[i] = *(const float4*)&W[(size_t)br * D_OUT + bc4 * 4];
    }

#pragma unroll 1
    for (int kb = 0; kb < D_IN / BKT; kb++) {
        // Store staged tile (convert to tf32 bit patterns).
#pragma unroll
        for (int i = 0; i < 4; i++) {
            int idx = tid + i * 256;
            int ar  = idx >> 3;
            int ac4 = (idx & 7) * 4;
            float4 a = aR[i];
            *(float4*)&As[ar][ac4] =
                make_float4(f2tf32(a.x), f2tf32(a.y), f2tf32(a.z), f2tf32(a.w));
            int br  = idx >> 5;
            int bc4 = (idx & 31) * 4;
            float4 b = bR[i];
            *(float4*)&Bs[br][bc4] =
                make_float4(f2tf32(b.x), f2tf32(b.y), f2tf32(b.z), f2tf32(b.w));
        }
        __syncthreads();

        // Prefetch next slab while MMAs run.
        if (kb + 1 < D_IN / BKT) {
            int k0 = (kb + 1) * BKT;
#pragma unroll
            for (int i = 0; i < 4; i++) {
                int idx = tid + i * 256;
                int ar  = idx >> 3;
                int ac4 = idx & 7;
                int grow = block_row + ar;
                aR[i] = (grow < N_NODES)
                    ? *(const float4*)&X[(size_t)grow * D_IN + k0 + ac4 * 4]
                    : make_float4(0.f, 0.f, 0.f, 0.f);
                int br  = idx >> 5;
                int bc4 = idx & 31;
                bR[i] = *(const float4*)&W[(size_t)(k0 + br) * D_OUT + bc4 * 4];
            }
        }

        // 4 k8-steps of mma over this BK=32 slab.
#pragma unroll
        for (int ks = 0; ks < 4; ks++) {
            const int k0 = ks * 8;
            uint32_t afrag[2][4];
#pragma unroll
            for (int mt = 0; mt < 2; mt++) {
                int row = warp_m + mt * 16 + lq;
                afrag[mt][0] = __float_as_uint(As[row    ][k0 + lr    ]);
                afrag[mt][1] = __float_as_uint(As[row + 8][k0 + lr    ]);
                afrag[mt][2] = __float_as_uint(As[row    ][k0 + lr + 4]);
                afrag[mt][3] = __float_as_uint(As[row + 8][k0 + lr + 4]);
            }
#pragma unroll
            for (int nt = 0; nt < 8; nt++) {
                int n0 = warp_n + nt * 8;
                uint32_t b0 = __float_as_uint(Bs[k0 + lr    ][n0 + lq]);
                uint32_t b1 = __float_as_uint(Bs[k0 + lr + 4][n0 + lq]);
                mma_tf32(acc[0][nt], afrag[0], b0, b1);
                mma_tf32(acc[1][nt], afrag[1], b0, b1);
            }
        }
        __syncthreads();
    }

    // Epilogue: C fragment layout m16n8 -> c0/c1 at (row, 2c), c2/c3 at (row+8, 2c).
#pragma unroll
    for (int mt = 0; mt < 2; mt++) {
        int r0 = block_row + warp_m + mt * 16 + lq;
        int r1 = r0 + 8;
#pragma unroll
        for (int nt = 0; nt < 8; nt++) {
            int c = warp_n + nt * 8 + lr * 2;
            if (r0 < N_NODES)
                *(float2*)&g_support[(size_t)r0 * D_OUT + c] =
                    make_float2(acc[mt][nt][0], acc[mt][nt][1]);
            if (r1 < N_NODES)
                *(float2*)&g_support[(size_t)r1 * D_OUT + c] =
                    make_float2(acc[mt][nt][2], acc[mt][nt][3]);
        }
    }
}

// ---------------------------------------------------------------------------
// Kernel 2: out[n, :] = bias[:]   (initializes the poisoned output buffer)
// ---------------------------------------------------------------------------
__global__ __launch_bounds__(256) void bias_init_kernel(const float* __restrict__ bias,
                                                        float* __restrict__ out) {
    __shared__ float4 b4[D_OUT / 4];
    if (threadIdx.x < D_OUT / 4)
        b4[threadIdx.x] = *(const float4*)&bias[threadIdx.x * 4];
    __syncthreads();

    size_t total4 = (size_t)N_NODES * D_OUT / 4;
    size_t idx = (size_t)blockIdx.x * blockDim.x + threadIdx.x;
    size_t stride = (size_t)gridDim.x * blockDim.x;
    for (; idx < total4; idx += stride) {
        ((float4*)out)[idx] = b4[idx & (D_OUT / 4 - 1)];
    }
}

// ---------------------------------------------------------------------------
// Kernel 3: SpMM scatter (unchanged from the passing R6 kernel).
// adj_dst is SORTED: per-warp contiguous edge chunk, register accumulation,
// atomicAdd flush on segment boundaries. Indices are int32.
// ---------------------------------------------------------------------------
#define EDGES_PER_WARP 128

__global__ __launch_bounds__(256) void spmm_kernel(const int* __restrict__ src,
                                                   const int* __restrict__ dst,
                                                   const float* __restrict__ val,
                                                   float* __restrict__ out) {
    const int warp_id = (blockIdx.x * blockDim.x + threadIdx.x) >> 5;
    const int lane    = threadIdx.x & 31;
    const int lane4   = lane * 4;

    int e0 = warp_id * EDGES_PER_WARP;
    if (e0 >= N_EDGES) return;
    int e1 = e0 + EDGES_PER_WARP;
    if (e1 > N_EDGES) e1 = N_EDGES;

    float4 acc = make_float4(0.f, 0.f, 0.f, 0.f);

    int   cur_dst = dst[e0];
    int   nd = cur_dst;
    int   ns = src[e0];
    float nv = val[e0];

    for (int e = e0; e < e1; e++) {
        int   d = nd;
        int   s = ns;
        float v = nv;
        if (e + 1 < e1) {
            nd = dst[e + 1];
            ns = src[e + 1];
            nv = val[e + 1];
        }
        if (d != cur_dst) {
            if (cur_dst >= 0 && cur_dst < N_NODES) {
                float* o = &out[(size_t)cur_dst * D_OUT + lane4];
                atomicAdd(&o[0], acc.x);
                atomicAdd(&o[1], acc.y);
                atomicAdd(&o[2], acc.z);
                atomicAdd(&o[3], acc.w);
            }
            acc = make_float4(0.f, 0.f, 0.f, 0.f);
            cur_dst = d;
        }
        if (s >= 0 && s < N_NODES) {
            float4 sup = *(const float4*)&g_support[(size_t)s * D_OUT + lane4];
            acc.x += v * sup.x;
            acc.y += v * sup.y;
            acc.z += v * sup.z;
            acc.w += v * sup.w;
        }
    }
    if (cur_dst >= 0 && cur_dst < N_NODES) {
        float* o = &out[(size_t)cur_dst * D_OUT + lane4];
        atomicAdd(&o[0], acc.x);
        atomicAdd(&o[1], acc.y);
        atomicAdd(&o[2], acc.z);
        atomicAdd(&o[3], acc.w);
    }
}

// ---------------------------------------------------------------------------
// Launch
// Inputs (metadata order): x, adj_src, adj_dst, adj_val, weight, bias
// ---------------------------------------------------------------------------
extern "C" void kernel_launch(void* const* d_in, const int* in_sizes, int n_in,
                              void* d_out, int out_size) {
    const float* x      = (const float*)d_in[0];
    const int*   adjsrc = (const int*)d_in[1];
    const int*   adjdst = (const int*)d_in[2];
    const float* adjval = (const float*)d_in[3];
    const float* weight = (const float*)d_in[4];
    const float* bias   = (const float*)d_in[5];
    float*       out    = (float*)d_out;

    // 1) support = X @ W  (tf32 tensor cores)
    int gemm_blocks = (N_NODES + BM - 1) / BM;   // 391
    gemm_tc_kernel<<<gemm_blocks, 256>>>(x, weight);

    // 2) out = bias (broadcast)
    bias_init_kernel<<<1184, 256>>>(bias, out);

    // 3) out += segment_sum(val * support[src], dst)
    int n_warps  = (N_EDGES + EDGES_PER_WARP - 1) / EDGES_PER_WARP;  // 6250
    int n_blocks = (n_warps + 7) / 8;                                // 782
    spmm_kernel<<<n_blocks, 256>>>(adjsrc, adjdst, adjval, out);
}

// round 9
// speedup vs baseline: 1.4287x; 1.0298x over previous
#include <cuda_runtime.h>
#include <cuda_fp16.h>
#include <cstdint>

// Problem constants (from reference)
#define N_NODES 50000
#define N_EDGES 800000
#define D_IN    128
#define D_OUT   128

// Scratch: support = X @ W stored as fp16 (12.8 MB) -> halves SpMM gather bytes.
// fp16 rounding RMS rel err ~1.4e-4, quadrature with tf32's 3e-4 stays << 1e-3.
__device__ __half g_support[(size_t)N_NODES * D_OUT];

// ---------------------------------------------------------------------------
// Kernel 1: tf32 tensor-core GEMM  support[M,128] = X[M,128] @ W[128,128]
// BM=128, BK=32, 256 threads = 8 warps in a 4(m) x 2(n) grid.
// Warp tile 32x64 = 2 m-tiles x 8 n-tiles of mma.m16n8k8.tf32.
// fp32 -> tf32 (round-to-nearest) at smem store; fp32 accumulate; fp16 out.
// ---------------------------------------------------------------------------
#define BM   128
#define BKT  32
#define APAD 4   // As stride 36 floats: conflict-free fragment reads
#define BPAD 4   // Bs stride 132 floats: conflict-free fragment reads

__device__ __forceinline__ float f2tf32(float x) {
    uint32_t u;
    asm("cvt.rna.tf32.f32 %0, %1;" : "=r"(u) : "f"(x));
    return __uint_as_float(u);
}

__device__ __forceinline__ void mma_tf32(float* c, const uint32_t* a,
                                         uint32_t b0, uint32_t b1) {
    asm volatile(
        "mma.sync.aligned.m16n8k8.row.col.f32.tf32.tf32.f32 "
        "{%0,%1,%2,%3}, {%4,%5,%6,%7}, {%8,%9}, {%0,%1,%2,%3};\n"
        : "+f"(c[0]), "+f"(c[1]), "+f"(c[2]), "+f"(c[3])
        : "r"(a[0]), "r"(a[1]), "r"(a[2]), "r"(a[3]), "r"(b0), "r"(b1));
}

__global__ __launch_bounds__(256, 2) void gemm_tc_kernel(const float* __restrict__ X,
                                                         const float* __restrict__ W) {
    __shared__ float As[BM][BKT + APAD];     // 128 x 36  (18.4 KB)
    __shared__ float Bs[BKT][D_OUT + BPAD];  // 32 x 132  (16.9 KB)

    const int tid  = threadIdx.x;
    const int wid  = tid >> 5;
    const int lane = tid & 31;
    const int block_row = blockIdx.x * BM;

    const int warp_m = (wid & 3) * 32;   // 0,32,64,96
    const int warp_n = (wid >> 2) * 64;  // 0,64
    const int lq = lane >> 2;            // 0..7
    const int lr = lane & 3;             // 0..3

    float acc[2][8][4];
#pragma unroll
    for (int mt = 0; mt < 2; mt++)
#pragma unroll
        for (int nt = 0; nt < 8; nt++)
#pragma unroll
            for (int i = 0; i < 4; i++) acc[mt][nt][i] = 0.0f;

    // Register-staged tiles. A: 128x32 = 1024 float4 -> 4/thread.
    //                        B:  32x128 = 1024 float4 -> 4/thread.
    float4 aR[4], bR[4];

    // Prefetch kb=0.
#pragma unroll
    for (int i = 0; i < 4; i++) {
        int idx = tid + i * 256;
        int ar  = idx >> 3;          // 0..127
        int ac4 = idx & 7;           // 0..7
        int grow = block_row + ar;
        aR[i] = (grow < N_NODES)
            ? *(const float4*)&X[(size_t)grow * D_IN + ac4 * 4]
            : make_float4(0.f, 0.f, 0.f, 0.f);
        int br  = idx >> 5;          // 0..31
        int bc4 = idx & 31;          // 0..31
        bR[i] = *(const float4*)&W[(size_t)br * D_OUT + bc4 * 4];
    }

#pragma unroll 1
    for (int kb = 0; kb < D_IN / BKT; kb++) {
        // Store staged tile (convert to tf32 bit patterns).
#pragma unroll
        for (int i = 0; i < 4; i++) {
            int idx = tid + i * 256;
            int ar  = idx >> 3;
            int ac4 = (idx & 7) * 4;
            float4 a = aR[i];
            *(float4*)&As[ar][ac4] =
                make_float4(f2tf32(a.x), f2tf32(a.y), f2tf32(a.z), f2tf32(a.w));
            int br  = idx >> 5;
            int bc4 = (idx & 31) * 4;
            float4 b = bR[i];
            *(float4*)&Bs[br][bc4] =
                make_float4(f2tf32(b.x), f2tf32(b.y), f2tf32(b.z), f2tf32(b.w));
        }
        __syncthreads();

        // Prefetch next slab while MMAs run.
        if (kb + 1 < D_IN / BKT) {
            int k0 = (kb + 1) * BKT;
#pragma unroll
            for (int i = 0; i < 4; i++) {
                int idx = tid + i * 256;
                int ar  = idx >> 3;
                int ac4 = idx & 7;
                int grow = block_row + ar;
                aR[i] = (grow < N_NODES)
                    ? *(const float4*)&X[(size_t)grow * D_IN + k0 + ac4 * 4]
                    : make_float4(0.f, 0.f, 0.f, 0.f);
                int br  = idx >> 5;
                int bc4 = idx & 31;
                bR[i] = *(const float4*)&W[(size_t)(k0 + br) * D_OUT + bc4 * 4];
            }
        }

        // 4 k8-steps of mma over this BK=32 slab.
#pragma unroll
        for (int ks = 0; ks < 4; ks++) {
            const int k0 = ks * 8;
            uint32_t afrag[2][4];
#pragma unroll
            for (int mt = 0; mt < 2; mt++) {
                int row = warp_m + mt * 16 + lq;
                afrag[mt][0] = __float_as_uint(As[row    ][k0 + lr    ]);
                afrag[mt][1] = __float_as_uint(As[row + 8][k0 + lr    ]);
                afrag[mt][2] = __float_as_uint(As[row    ][k0 + lr + 4]);
                afrag[mt][3] = __float_as_uint(As[row + 8][k0 + lr + 4]);
            }
#pragma unroll
            for (int nt = 0; nt < 8; nt++) {
                int n0 = warp_n + nt * 8;
                uint32_t b0 = __float_as_uint(Bs[k0 + lr    ][n0 + lq]);
                uint32_t b1 = __float_as_uint(Bs[k0 + lr + 4][n0 + lq]);
                mma_tf32(acc[0][nt], afrag[0], b0, b1);
                mma_tf32(acc[1][nt], afrag[1], b0, b1);
            }
        }
        __syncthreads();
    }

    // Epilogue: fragment pair (c0,c1) = cols (c, c+1) row r0; (c2,c3) row r1.
    // Two consecutive cols -> one __half2 store (4B, aligned: c is even).
#pragma unroll
    for (int mt = 0; mt < 2; mt++) {
        int r0 = block_row + warp_m + mt * 16 + lq;
        int r1 = r0 + 8;
#pragma unroll
        for (int nt = 0; nt < 8; nt++) {
            int c = warp_n + nt * 8 + lr * 2;
            if (r0 < N_NODES)
                *(__half2*)&g_support[(size_t)r0 * D_OUT + c] =
                    __floats2half2_rn(acc[mt][nt][0], acc[mt][nt][1]);
            if (r1 < N_NODES)
                *(__half2*)&g_support[(size_t)r1 * D_OUT + c] =
                    __floats2half2_rn(acc[mt][nt][2], acc[mt][nt][3]);
        }
    }
}

// ---------------------------------------------------------------------------
// Kernel 2: out[n, :] = bias[:]   (initializes the poisoned output buffer)
// ---------------------------------------------------------------------------
__global__ __launch_bounds__(256) void bias_init_kernel(const float* __restrict__ bias,
                                                        float* __restrict__ out) {
    __shared__ float4 b4[D_OUT / 4];
    if (threadIdx.x < D_OUT / 4)
        b4[threadIdx.x] = *(const float4*)&bias[threadIdx.x * 4];
    __syncthreads();

    size_t total4 = (size_t)N_NODES * D_OUT / 4;
    size_t idx = (size_t)blockIdx.x * blockDim.x + threadIdx.x;
    size_t stride = (size_t)gridDim.x * blockDim.x;
    for (; idx < total4; idx += stride) {
        ((float4*)out)[idx] = b4[idx & (D_OUT / 4 - 1)];
    }
}

// ---------------------------------------------------------------------------
// Kernel 3: SpMM scatter.  adj_dst is SORTED: per-warp contiguous edge chunk,
// register accumulation (fp32), atomicAdd flush on segment boundaries.
// Gather is fp16 (8B/lane instead of 16B) -> half the L2 traffic.
// ---------------------------------------------------------------------------
#define EDGES_PER_WARP 128

__global__ __launch_bounds__(256) void spmm_kernel(const int* __restrict__ src,
                                                   const int* __restrict__ dst,
                                                   const float* __restrict__ val,
                                                   float* __restrict__ out) {
    const int warp_id = (blockIdx.x * blockDim.x + threadIdx.x) >> 5;
    const int lane    = threadIdx.x & 31;
    const int lane4   = lane * 4;

    int e0 = warp_id * EDGES_PER_WARP;
    if (e0 >= N_EDGES) return;
    int e1 = e0 + EDGES_PER_WARP;
    if (e1 > N_EDGES) e1 = N_EDGES;

    float4 acc = make_float4(0.f, 0.f, 0.f, 0.f);

    // Prefetched edge metadata (uniform across warp -> broadcast loads).
    int   cur_dst = dst[e0];
    int   nd = cur_dst;
    int   ns = src[e0];
    float nv = val[e0];

    for (int e = e0; e < e1; e++) {
        int   d = nd;
        int   s = ns;
        float v = nv;
        if (e + 1 < e1) {
            nd = dst[e + 1];
            ns = src[e + 1];
            nv = val[e + 1];
        }
        if (d != cur_dst) {
            if (cur_dst >= 0 && cur_dst < N_NODES) {
                float* o = &out[(size_t)cur_dst * D_OUT + lane4];
                atomicAdd(&o[0], acc.x);
                atomicAdd(&o[1], acc.y);
                atomicAdd(&o[2], acc.z);
                atomicAdd(&o[3], acc.w);
            }
            acc = make_float4(0.f, 0.f, 0.f, 0.f);
            cur_dst = d;
        }
        if (s >= 0 && s < N_NODES) {
            // 4 halves = 8 bytes per lane.
            uint2 u = *(const uint2*)&g_support[(size_t)s * D_OUT + lane4];
            float2 f0 = __half22float2(*(__half2*)&u.x);
            float2 f1 = __half22float2(*(__half2*)&u.y);
            acc.x += v * f0.x;
            acc.y += v * f0.y;
            acc.z += v * f1.x;
            acc.w += v * f1.y;
        }
    }
    if (cur_dst >= 0 && cur_dst < N_NODES) {
        float* o = &out[(size_t)cur_dst * D_OUT + lane4];
        atomicAdd(&o[0], acc.x);
        atomicAdd(&o[1], acc.y);
        atomicAdd(&o[2], acc.z);
        atomicAdd(&o[3], acc.w);
    }
}

// ---------------------------------------------------------------------------
// Launch
// Inputs (metadata order): x, adj_src, adj_dst, adj_val, weight, bias
// ---------------------------------------------------------------------------
extern "C" void kernel_launch(void* const* d_in, const int* in_sizes, int n_in,
                              void* d_out, int out_size) {
    const float* x      = (const float*)d_in[0];
    const int*   adjsrc = (const int*)d_in[1];
    const int*   adjdst = (const int*)d_in[2];
    const float* adjval = (const float*)d_in[3];
    const float* weight = (const float*)d_in[4];
    const float* bias   = (const float*)d_in[5];
    float*       out    = (float*)d_out;

    // 1) support = X @ W  (tf32 tensor cores, fp16 output)
    int gemm_blocks = (N_NODES + BM - 1) / BM;   // 391
    gemm_tc_kernel<<<gemm_blocks, 256>>>(x, weight);

    // 2) out = bias (broadcast)
    bias_init_kernel<<<1184, 256>>>(bias, out);

    // 3) out += segment_sum(val * support[src], dst)
    int n_warps  = (N_EDGES + EDGES_PER_WARP - 1) / EDGES_PER_WARP;  // 6250
    int n_blocks = (n_warps + 7) / 8;                                // 782
    spmm_kernel<<<n_blocks, 256>>>(adjsrc, adjdst, adjval, out);
}

// round 10
// speedup vs baseline: 1.5198x; 1.0638x over previous
#include <cuda_runtime.h>
#include <cuda_fp16.h>
#include <cstdint>

// Problem constants (from reference)
#define N_NODES 50000
#define N_EDGES 800000
#define D_IN    128
#define D_OUT   128

// Scratch: support = X @ W stored as fp16 (12.8 MB).
__device__ __half g_support[(size_t)N_NODES * D_OUT];

// ---------------------------------------------------------------------------
// Kernel 1: tf32 tensor-core GEMM  support[M,128] = X[M,128] @ W[128,128]
// (unchanged from the 72.0us passing kernel)
// ---------------------------------------------------------------------------
#define BM   128
#define BKT  32
#define APAD 4
#define BPAD 4

__device__ __forceinline__ float f2tf32(float x) {
    uint32_t u;
    asm("cvt.rna.tf32.f32 %0, %1;" : "=r"(u) : "f"(x));
    return __uint_as_float(u);
}

__device__ __forceinline__ void mma_tf32(float* c, const uint32_t* a,
                                         uint32_t b0, uint32_t b1) {
    asm volatile(
        "mma.sync.aligned.m16n8k8.row.col.f32.tf32.tf32.f32 "
        "{%0,%1,%2,%3}, {%4,%5,%6,%7}, {%8,%9}, {%0,%1,%2,%3};\n"
        : "+f"(c[0]), "+f"(c[1]), "+f"(c[2]), "+f"(c[3])
        : "r"(a[0]), "r"(a[1]), "r"(a[2]), "r"(a[3]), "r"(b0), "r"(b1));
}

__global__ __launch_bounds__(256, 2) void gemm_tc_kernel(const float* __restrict__ X,
                                                         const float* __restrict__ W) {
    __shared__ float As[BM][BKT + APAD];     // 128 x 36
    __shared__ float Bs[BKT][D_OUT + BPAD];  // 32 x 132

    const int tid  = threadIdx.x;
    const int wid  = tid >> 5;
    const int lane = tid & 31;
    const int block_row = blockIdx.x * BM;

    const int warp_m = (wid & 3) * 32;
    const int warp_n = (wid >> 2) * 64;
    const int lq = lane >> 2;
    const int lr = lane & 3;

    float acc[2][8][4];
#pragma unroll
    for (int mt = 0; mt < 2; mt++)
#pragma unroll
        for (int nt = 0; nt < 8; nt++)
#pragma unroll
            for (int i = 0; i < 4; i++) acc[mt][nt][i] = 0.0f;

    float4 aR[4], bR[4];

#pragma unroll
    for (int i = 0; i < 4; i++) {
        int idx = tid + i * 256;
        int ar  = idx >> 3;
        int ac4 = idx & 7;
        int grow = block_row + ar;
        aR[i] = (grow < N_NODES)
            ? *(const float4*)&X[(size_t)grow * D_IN + ac4 * 4]
            : make_float4(0.f, 0.f, 0.f, 0.f);
        int br  = idx >> 5;
        int bc4 = idx & 31;
        bR[i] = *(const float4*)&W[(size_t)br * D_OUT + bc4 * 4];
    }

#pragma unroll 1
    for (int kb = 0; kb < D_IN / BKT; kb++) {
#pragma unroll
        for (int i = 0; i < 4; i++) {
            int idx = tid + i * 256;
            int ar  = idx >> 3;
            int ac4 = (idx & 7) * 4;
            float4 a = aR[i];
            *(float4*)&As[ar][ac4] =
                make_float4(f2tf32(a.x), f2tf32(a.y), f2tf32(a.z), f2tf32(a.w));
            int br  = idx >> 5;
            int bc4 = (idx & 31) * 4;
            float4 b = bR[i];
            *(float4*)&Bs[br][bc4] =
                make_float4(f2tf32(b.x), f2tf32(b.y), f2tf32(b.z), f2tf32(b.w));
        }
        __syncthreads();

        if (kb + 1 < D_IN / BKT) {
            int k0 = (kb + 1) * BKT;
#pragma unroll
            for (int i = 0; i < 4; i++) {
                int idx = tid + i * 256;
                int ar  = idx >> 3;
                int ac4 = idx & 7;
                int grow = block_row + ar;
                aR[i] = (grow < N_NODES)
                    ? *(const float4*)&X[(size_t)grow * D_IN + k0 + ac4 * 4]
                    : make_float4(0.f, 0.f, 0.f, 0.f);
                int br  = idx >> 5;
                int bc4 = idx & 31;
                bR[i] = *(const float4*)&W[(size_t)(k0 + br) * D_OUT + bc4 * 4];
            }
        }

#pragma unroll
        for (int ks = 0; ks < 4; ks++) {
            const int k0 = ks * 8;
            uint32_t afrag[2][4];
#pragma unroll
            for (int mt = 0; mt < 2; mt++) {
                int row = warp_m + mt * 16 + lq;
                afrag[mt][0] = __float_as_uint(As[row    ][k0 + lr    ]);
                afrag[mt][1] = __float_as_uint(As[row + 8][k0 + lr    ]);
                afrag[mt][2] = __float_as_uint(As[row    ][k0 + lr + 4]);
                afrag[mt][3] = __float_as_uint(As[row + 8][k0 + lr + 4]);
            }
#pragma unroll
            for (int nt = 0; nt < 8; nt++) {
                int n0 = warp_n + nt * 8;
                uint32_t b0 = __float_as_uint(Bs[k0 + lr    ][n0 + lq]);
                uint32_t b1 = __float_as_uint(Bs[k0 + lr + 4][n0 + lq]);
                mma_tf32(acc[0][nt], afrag[0], b0, b1);
                mma_tf32(acc[1][nt], afrag[1], b0, b1);
            }
        }
        __syncthreads();
    }

#pragma unroll
    for (int mt = 0; mt < 2; mt++) {
        int r0 = block_row + warp_m + mt * 16 + lq;
        int r1 = r0 + 8;
#pragma unroll
        for (int nt = 0; nt < 8; nt++) {
            int c = warp_n + nt * 8 + lr * 2;
            if (r0 < N_NODES)
                *(__half2*)&g_support[(size_t)r0 * D_OUT + c] =
                    __floats2half2_rn(acc[mt][nt][0], acc[mt][nt][1]);
            if (r1 < N_NODES)
                *(__half2*)&g_support[(size_t)r1 * D_OUT + c] =
                    __floats2half2_rn(acc[mt][nt][2], acc[mt][nt][3]);
        }
    }
}

// ---------------------------------------------------------------------------
// Kernel 2: out[n, :] = bias[:]
// ---------------------------------------------------------------------------
__global__ __launch_bounds__(256) void bias_init_kernel(const float* __restrict__ bias,
                                                        float* __restrict__ out) {
    __shared__ float4 b4[D_OUT / 4];
    if (threadIdx.x < D_OUT / 4)
        b4[threadIdx.x] = *(const float4*)&bias[threadIdx.x * 4];
    __syncthreads();

    size_t total4 = (size_t)N_NODES * D_OUT / 4;
    size_t idx = (size_t)blockIdx.x * blockDim.x + threadIdx.x;
    size_t stride = (size_t)gridDim.x * blockDim.x;
    for (; idx < total4; idx += stride) {
        ((float4*)out)[idx] = b4[idx & (D_OUT / 4 - 1)];
    }
}

// ---------------------------------------------------------------------------
// Kernel 3: SpMM scatter, UNROLL-4 for MLP.
// Round-9 finding: the gather loop was latency-bound at MLP=1 (~1 edge per
// ~250-cyc L2 round trip per warp). Now each iteration loads 4 edges' metadata
// as int4/float4 vectors (e0 is 128-aligned; 800000/128 = 6250 exact chunks)
// and issues 4 independent support gathers BEFORE any accumulation -> MLP=4.
// Segment flush logic runs per-edge after the gathers land (order preserved).
// ---------------------------------------------------------------------------
#define EDGES_PER_WARP 128

__global__ __launch_bounds__(256) void spmm_kernel(const int* __restrict__ src,
                                                   const int* __restrict__ dst,
                                                   const float* __restrict__ val,
                                                   float* __restrict__ out) {
    const int warp_id = (blockIdx.x * blockDim.x + threadIdx.x) >> 5;
    const int lane    = threadIdx.x & 31;
    const int lane4   = lane * 4;

    const int e0 = warp_id * EDGES_PER_WARP;
    if (e0 >= N_EDGES) return;
    const int e1 = e0 + EDGES_PER_WARP;   // always full: 800000 % 128 == 0

    float4 acc = make_float4(0.f, 0.f, 0.f, 0.f);
    int cur_dst = dst[e0];

    const uint2 zero2 = make_uint2(0u, 0u);

    for (int e = e0; e < e1; e += 4) {
        // Vector metadata loads (16B aligned: e0 % 4 == 0).
        const int4   s4 = *(const int4*)&src[e];
        const int4   d4 = *(const int4*)&dst[e];
        const float4 v4 = *(const float4*)&val[e];

        // Issue all 4 gathers up front (independent -> 4 in flight).
        uint2 g0 = ((unsigned)s4.x < N_NODES)
            ? *(const uint2*)&g_support[(size_t)s4.x * D_OUT + lane4] : zero2;
        uint2 g1 = ((unsigned)s4.y < N_NODES)
            ? *(const uint2*)&g_support[(size_t)s4.y * D_OUT + lane4] : zero2;
        uint2 g2 = ((unsigned)s4.z < N_NODES)
            ? *(const uint2*)&g_support[(size_t)s4.z * D_OUT + lane4] : zero2;
        uint2 g3 = ((unsigned)s4.w < N_NODES)
            ? *(const uint2*)&g_support[(size_t)s4.w * D_OUT + lane4] : zero2;

        const int   ds[4] = {d4.x, d4.y, d4.z, d4.w};
        const float vs[4] = {v4.x, v4.y, v4.z, v4.w};
        const uint2 gs[4] = {g0, g1, g2, g3};

#pragma unroll
        for (int i = 0; i < 4; i++) {
            if (ds[i] != cur_dst) {
                if ((unsigned)cur_dst < N_NODES) {
                    float* o = &out[(size_t)cur_dst * D_OUT + lane4];
                    atomicAdd(&o[0], acc.x);
                    atomicAdd(&o[1], acc.y);
                    atomicAdd(&o[2], acc.z);
                    atomicAdd(&o[3], acc.w);
                }
                acc = make_float4(0.f, 0.f, 0.f, 0.f);
                cur_dst = ds[i];
            }
            float2 f0 = __half22float2(*(const __half2*)&gs[i].x);
            float2 f1 = __half22float2(*(const __half2*)&gs[i].y);
            float v = vs[i];
            acc.x += v * f0.x;
            acc.y += v * f0.y;
            acc.z += v * f1.x;
            acc.w += v * f1.y;
        }
    }

    if ((unsigned)cur_dst < N_NODES) {
        float* o = &out[(size_t)cur_dst * D_OUT + lane4];
        atomicAdd(&o[0], acc.x);
        atomicAdd(&o[1], acc.y);
        atomicAdd(&o[2], acc.z);
        atomicAdd(&o[3], acc.w);
    }
}

// ---------------------------------------------------------------------------
// Launch
// Inputs (metadata order): x, adj_src, adj_dst, adj_val, weight, bias
// ---------------------------------------------------------------------------
extern "C" void kernel_launch(void* const* d_in, const int* in_sizes, int n_in,
                              void* d_out, int out_size) {
    const float* x      = (const float*)d_in[0];
    const int*   adjsrc = (const int*)d_in[1];
    const int*   adjdst = (const int*)d_in[2];
    const float* adjval = (const float*)d_in[3];
    const float* weight = (const float*)d_in[4];
    const float* bias   = (const float*)d_in[5];
    float*       out    = (float*)d_out;

    // 1) support = X @ W  (tf32 tensor cores, fp16 output)
    int gemm_blocks = (N_NODES + BM - 1) / BM;   // 391
    gemm_tc_kernel<<<gemm_blocks, 256>>>(x, weight);

    // 2) out = bias (broadcast)
    bias_init_kernel<<<1184, 256>>>(bias, out);

    // 3) out += segment_sum(val * support[src], dst)
    int n_warps  = (N_EDGES + EDGES_PER_WARP - 1) / EDGES_PER_WARP;  // 6250
    int n_blocks = (n_warps + 7) / 8;                                // 782
    spmm_kernel<<<n_blocks, 256>>>(adjsrc, adjdst, adjval, out);
}